// round 13
// baseline (speedup 1.0000x reference)
#include <cuda_runtime.h>
#include <cuda_bf16.h>
#include <cstdint>

#define Bz 2
#define Lz 1024
#define Mz (Bz*Lz)      // 2048
#define DM 768
#define DI 1536
#define DI2 3072
#define DS 16
#define RK 48
#define RKP 64
#define XDB 80
#define NSPK 16         // split-K factor for xdbl GEMM

// ---------------- fp32 scratch ----------------
__device__ __align__(16) float g_xz[Mz*DI2];
__device__ __align__(16) float g_dt[Mz*DI];
__device__ __align__(16) float g_xdp[NSPK*Mz*XDB];   // split-K partials for xdbl
__device__ __align__(16) float g_knq[Mz*48];
__device__ __align__(16) float2 g_ms[Mz];            // per-(b,t): (s, kk)

// ---------------- bf16 hi/lo pre-split operands ----------------
__device__ __align__(16) __nv_bfloat16 g_hs_h[Mz*DM],   g_hs_l[Mz*DM];
__device__ __align__(16) __nv_bfloat16 g_ipw_h[DI2*DM], g_ipw_l[DI2*DM];
__device__ __align__(16) __nv_bfloat16 g_xact_h[Mz*DI], g_xact_l[Mz*DI];
__device__ __align__(16) __nv_bfloat16 g_xpw_h[XDB*DI], g_xpw_l[XDB*DI];
__device__ __align__(16) __nv_bfloat16 g_dtl_h[Mz*RKP], g_dtl_l[Mz*RKP];
__device__ __align__(16) __nv_bfloat16 g_dthw_h[DI*RKP],g_dthw_l[DI*RKP];
__device__ __align__(16) __nv_bfloat16 g_yg_h[Mz*DI],   g_yg_l[Mz*DI];
__device__ __align__(16) __nv_bfloat16 g_opw_h[DM*DI],  g_opw_l[DM*DI];

// ---------------- helpers ----------------
__device__ __forceinline__ void ldsm4(uint32_t& r0, uint32_t& r1, uint32_t& r2, uint32_t& r3,
                                      uint32_t saddr) {
    asm volatile("ldmatrix.sync.aligned.m8n8.x4.shared.b16 {%0,%1,%2,%3}, [%4];"
                 : "=r"(r0), "=r"(r1), "=r"(r2), "=r"(r3) : "r"(saddr));
}
__device__ __forceinline__ void mma_bf16(float* c, const uint32_t* a, const uint32_t* b) {
    asm volatile(
        "mma.sync.aligned.m16n8k16.row.col.f32.bf16.bf16.f32 "
        "{%0,%1,%2,%3}, {%4,%5,%6,%7}, {%8,%9}, {%0,%1,%2,%3};"
        : "+f"(c[0]), "+f"(c[1]), "+f"(c[2]), "+f"(c[3])
        : "r"(a[0]), "r"(a[1]), "r"(a[2]), "r"(a[3]), "r"(b[0]), "r"(b[1]));
}
__device__ __forceinline__ void cpa16(uint32_t dst, const void* src, uint32_t sz) {
    asm volatile("cp.async.cg.shared.global [%0], [%1], 16, %2;" :: "r"(dst), "l"(src), "r"(sz));
}
__device__ __forceinline__ void cpa16u(uint32_t dst, const void* src) {
    asm volatile("cp.async.cg.shared.global [%0], [%1], 16;" :: "r"(dst), "l"(src));
}
__device__ __forceinline__ void cp_commit() { asm volatile("cp.async.commit_group;"); }

// ================= fused split kernel (5 segments; seg 4 = pad 48->64) =================
__global__ __launch_bounds__(256)
void split5_kernel(const float* __restrict__ s0, __nv_bfloat16* __restrict__ h0,
                   __nv_bfloat16* __restrict__ l0, int n0, int b0,
                   const float* __restrict__ s1, __nv_bfloat16* __restrict__ h1,
                   __nv_bfloat16* __restrict__ l1, int n1, int b1,
                   const float* __restrict__ s2, __nv_bfloat16* __restrict__ h2,
                   __nv_bfloat16* __restrict__ l2, int n2, int b2,
                   const float* __restrict__ s3, __nv_bfloat16* __restrict__ h3,
                   __nv_bfloat16* __restrict__ l3, int n3, int b3,
                   const float* __restrict__ s4, __nv_bfloat16* __restrict__ h4,
                   __nv_bfloat16* __restrict__ l4, int n4) {
    int blk = blockIdx.x;
    if (blk >= b3) {
        int i = (blk - b3) * 256 + threadIdx.x;
        if (i < n4) {
            int r = i >> 6, c = i & 63;   // RKP = 64
            float v = (c < RK) ? s4[(size_t)r * RK + c] : 0.f;
            __nv_bfloat16 h = __float2bfloat16(v);
            h4[i] = h;
            l4[i] = __float2bfloat16(v - __bfloat162float(h));
        }
        return;
    }
    const float* src; __nv_bfloat16 *dh, *dl; int n, i;
    if (blk < b0)      { src = s0; dh = h0; dl = l0; n = n0; i = blk * 256 + threadIdx.x; }
    else if (blk < b1) { src = s1; dh = h1; dl = l1; n = n1; i = (blk - b0) * 256 + threadIdx.x; }
    else if (blk < b2) { src = s2; dh = h2; dl = l2; n = n2; i = (blk - b1) * 256 + threadIdx.x; }
    else               { src = s3; dh = h3; dl = l3; n = n3; i = (blk - b2) * 256 + threadIdx.x; }
    if (i < n) {
        float v = src[i];
        __nv_bfloat16 h = __float2bfloat16(v);
        dh[i] = h;
        dl[i] = __float2bfloat16(v - __bfloat162float(h));
    }
}

// ================= bf16x3 3-stage swizzled GEMM: C[M,N] = A[M,K] * B[N,K]^T =================
// 128x128 tile, XOR-swizzled 64B rows, stage 32KB x3, safe single-barrier pipeline.
__global__ __launch_bounds__(256, 2)
void mma_gemm(const __nv_bfloat16* __restrict__ Agh, const __nv_bfloat16* __restrict__ Agl,
              const __nv_bfloat16* __restrict__ Bgh, const __nv_bfloat16* __restrict__ Bgl,
              float* __restrict__ C, int N, int Kc, int Ktot, int ldc, int partStride) {
    extern __shared__ __align__(16) ushort smbuf[];
    int tid = threadIdx.x, wid = tid >> 5, lane = tid & 31;
    int row0 = blockIdx.y << 7, col0 = blockIdx.x << 7;
    int wm = (wid >> 2) << 6, wn = (wid & 3) << 5;
    int koff = blockIdx.z * Kc;
    C += (size_t)blockIdx.z * partStride;
    uint32_t sbase = (uint32_t)__cvta_generic_to_shared(smbuf);
    bool wActive = (col0 + wn) < N;

    int c0 = tid, c1 = tid + 256;
    int r0 = c0 >> 2, ch0 = c0 & 3, o0 = ch0 << 3;
    int r1 = c1 >> 2, ch1 = c1 & 3, o1 = ch1 << 3;
    int br0 = col0 + r0, br1 = col0 + r1;
    uint32_t s0 = br0 < N ? 16u : 0u, s1 = br1 < N ? 16u : 0u;
    size_t a0b = (size_t)(row0 + r0) * Ktot + koff + o0;
    size_t a1b = (size_t)(row0 + r1) * Ktot + koff + o1;
    size_t b0b = (size_t)(br0 < N ? br0 : 0) * Ktot + koff + o0;
    size_t b1b = (size_t)(br1 < N ? br1 : 0) * Ktot + koff + o1;
    uint32_t d0 = (uint32_t)(r0 * 64 + ((ch0 ^ ((r0 >> 1) & 3)) << 4));
    uint32_t d1 = (uint32_t)(r1 * 64 + ((ch1 ^ ((r1 >> 1) & 3)) << 4));

    uint32_t swa = (uint32_t)(((lane & 15) >> 1) & 3);
    uint32_t cgA = (uint32_t)(lane >> 4);
    uint32_t aRow = (uint32_t)((wm + (lane & 15)) * 64);
    uint32_t swb = (uint32_t)(((lane & 7) >> 1) & 3);
    uint32_t cgB = (uint32_t)((lane >> 3) & 1);
    uint32_t bRow = (uint32_t)((wn + ((lane >> 4) << 3) + (lane & 7)) * 64);

    float acc[4][4][4];
#pragma unroll
    for (int i = 0; i < 4; i++)
#pragma unroll
        for (int j = 0; j < 4; j++)
#pragma unroll
            for (int r = 0; r < 4; r++) acc[i][j][r] = 0.f;

    int niter = Kc >> 5;

    auto issue = [&](int s) {
        uint32_t sb = sbase + (uint32_t)((s % 3) * 32768);
        int ko = s << 5;
        cpa16(sb + d0,         Agh + a0b + ko, 16);
        cpa16(sb + d1,         Agh + a1b + ko, 16);
        cpa16(sb + 8192 + d0,  Agl + a0b + ko, 16);
        cpa16(sb + 8192 + d1,  Agl + a1b + ko, 16);
        cpa16(sb + 16384 + d0, Bgh + b0b + ko, s0);
        cpa16(sb + 16384 + d1, Bgh + b1b + ko, s1);
        cpa16(sb + 24576 + d0, Bgl + b0b + ko, s0);
        cpa16(sb + 24576 + d1, Bgl + b1b + ko, s1);
    };

    issue(0); cp_commit();
    if (niter > 1) { issue(1); cp_commit(); }

    for (int it = 0; it < niter; it++) {
        if (it + 1 < niter) asm volatile("cp.async.wait_group 1;");
        else                asm volatile("cp.async.wait_group 0;");
        __syncthreads();
        if (it + 2 < niter) { issue(it + 2); cp_commit(); }

        if (wActive) {
            uint32_t stg = sbase + (uint32_t)((it % 3) * 32768);
#pragma unroll
            for (int kk = 0; kk < 2; kk++) {
                uint32_t ca = ((((uint32_t)(kk << 1) + cgA) ^ swa) << 4);
                uint32_t cb = ((((uint32_t)(kk << 1) + cgB) ^ swb) << 4);
                uint32_t a[4][4], bh[4][2], bl[4][2];
#pragma unroll
                for (int mt = 0; mt < 4; mt++)
                    ldsm4(a[mt][0], a[mt][1], a[mt][2], a[mt][3],
                          stg + aRow + (uint32_t)(mt * 1024) + ca);
#pragma unroll
                for (int g = 0; g < 2; g++) {
                    uint32_t q0, q1, q2, q3;
                    ldsm4(q0, q1, q2, q3, stg + 16384 + bRow + (uint32_t)(g * 1024) + cb);
                    bh[2 * g][0] = q0; bh[2 * g][1] = q1;
                    bh[2 * g + 1][0] = q2; bh[2 * g + 1][1] = q3;
                    ldsm4(q0, q1, q2, q3, stg + 24576 + bRow + (uint32_t)(g * 1024) + cb);
                    bl[2 * g][0] = q0; bl[2 * g][1] = q1;
                    bl[2 * g + 1][0] = q2; bl[2 * g + 1][1] = q3;
                }
#pragma unroll
                for (int mt = 0; mt < 4; mt++)
#pragma unroll
                    for (int ng = 0; ng < 4; ng++) mma_bf16(acc[mt][ng], a[mt], bh[ng]); // hi*hi
#pragma unroll
                for (int mt = 0; mt < 4; mt++)
#pragma unroll
                    for (int ng = 0; ng < 4; ng++) mma_bf16(acc[mt][ng], a[mt], bl[ng]); // hi*lo
#pragma unroll
                for (int mt = 0; mt < 4; mt++)
                    ldsm4(a[mt][0], a[mt][1], a[mt][2], a[mt][3],
                          stg + 8192 + aRow + (uint32_t)(mt * 1024) + ca);
#pragma unroll
                for (int mt = 0; mt < 4; mt++)
#pragma unroll
                    for (int ng = 0; ng < 4; ng++) mma_bf16(acc[mt][ng], a[mt], bh[ng]); // lo*hi
            }
        }
    }

    int cr = lane >> 2, cc = (lane & 3) << 1;
#pragma unroll
    for (int mt = 0; mt < 4; mt++)
#pragma unroll
        for (int ng = 0; ng < 4; ng++) {
            int row = row0 + wm + (mt << 4) + cr;
            int col = col0 + wn + (ng << 3) + cc;
            if (col < N) {
                *reinterpret_cast<float2*>(C + (size_t)row * ldc + col) =
                    make_float2(acc[mt][ng][0], acc[mt][ng][1]);
                *reinterpret_cast<float2*>(C + (size_t)(row + 8) * ldc + col) =
                    make_float2(acc[mt][ng][2], acc[mt][ng][3]);
            }
        }
}

// ================= xdbl split-K reduce + scatter (knq + dtl split/pad) =================
__global__ __launch_bounds__(256)
void xdbl_reduce_kernel() {
    int i = blockIdx.x * 256 + threadIdx.x;
    if (i >= Mz * 96) return;
    int r = i / 96, c = i - r * 96;
    if (c < 48) {
        float v = 0.f;
#pragma unroll
        for (int z = 0; z < NSPK; z++) v += g_xdp[(size_t)z * Mz * XDB + (size_t)r * XDB + c];
        __nv_bfloat16 h = __float2bfloat16(v);
        g_dtl_h[(size_t)r * RKP + c] = h;
        g_dtl_l[(size_t)r * RKP + c] = __float2bfloat16(v - __bfloat162float(h));
    } else if (c < 64) {
        g_dtl_h[(size_t)r * RKP + c] = __float2bfloat16(0.f);
        g_dtl_l[(size_t)r * RKP + c] = __float2bfloat16(0.f);
    } else if (c < 80) {
        int sc = c - 16;
        float v = 0.f;
#pragma unroll
        for (int z = 0; z < NSPK; z++) v += g_xdp[(size_t)z * Mz * XDB + (size_t)r * XDB + sc];
        g_knq[(size_t)r * 48 + (c - 64)] = v;
        g_knq[(size_t)r * 48 + 16 + (c - 64)] = v * v;
    } else {
        int sc = c - 16;
        float v = 0.f;
#pragma unroll
        for (int z = 0; z < NSPK; z++) v += g_xdp[(size_t)z * Mz * XDB + (size_t)r * XDB + sc];
        g_knq[(size_t)r * 48 + 32 + (c - 80)] = v;
    }
}

// ================= depthwise causal conv (k=4) + SiLU -> bf16 hi/lo only =================
__global__ __launch_bounds__(128)
void conv_silu_kernel(const float* __restrict__ conv_w,
                      const float* __restrict__ conv_b) {
    int d = blockIdx.x * 128 + threadIdx.x;
    int t0 = blockIdx.y * 16;
    int b = blockIdx.z;
    size_t base = (size_t)b * Lz;

    float xv[19];
#pragma unroll
    for (int i = 0; i < 19; i++) {
        int t = t0 - 3 + i;
        xv[i] = (t >= 0) ? g_xz[(base + t) * DI2 + d] : 0.f;
    }
    float w0 = conv_w[d * 4 + 0], w1 = conv_w[d * 4 + 1];
    float w2 = conv_w[d * 4 + 2], w3 = conv_w[d * 4 + 3];
    float bias = conv_b[d];
#pragma unroll
    for (int j = 0; j < 16; j++) {
        float a = fmaf(w0, xv[j], fmaf(w1, xv[j + 1], fmaf(w2, xv[j + 2], fmaf(w3, xv[j + 3], bias))));
        float s = a / (1.f + __expf(-a));
        size_t idx = (base + t0 + j) * DI + d;
        __nv_bfloat16 h = __float2bfloat16(s);
        g_xact_h[idx] = h;
        g_xact_l[idx] = __float2bfloat16(s - __bfloat162float(h));
    }
}

// ================= prep_scalar: per-(b,t) Newton-Schulz scalars only =================
__global__ __launch_bounds__(256)
void prep_scalar_kernel(const float* __restrict__ dt_bias) {
    int m = blockIdx.x;
    int tid = threadIdx.x;
    __shared__ float s_ksq[16];
    __shared__ float s_kk;
    __shared__ float red[8];

    if (tid < 16) s_ksq[tid] = g_knq[(size_t)m * 48 + 16 + tid];
    __syncthreads();
    if (tid == 0) {
        float kk = 0.f;
#pragma unroll
        for (int n = 0; n < 16; n++) kk += s_ksq[n];
        s_kk = kk;
    }
    __syncthreads();
    float kk = s_kk;

    float su = 0.f;
#pragma unroll
    for (int i = 0; i < 6; i++) {
        int d = tid + i * 256;
        float dtr = g_dt[(size_t)m * DI + d] + dt_bias[d];
        float s0 = 1.f / (1.f + __expf(-dtr));
        float dv = s0 / (1.f + s0 * kk);
        float x = __bfloat162float(g_xact_h[(size_t)m * DI + d]) +
                  __bfloat162float(g_xact_l[(size_t)m * DI + d]);
        float uu = dv * x;
        su += uu * uu;
    }
#pragma unroll
    for (int off = 16; off > 0; off >>= 1) su += __shfl_xor_sync(0xffffffffu, su, off);
    if ((tid & 31) == 0) red[tid >> 5] = su;
    __syncthreads();
    if (tid == 0) {
        float sut = 0.f;
#pragma unroll
        for (int i = 0; i < 8; i++) sut += red[i];
        float Nn = sqrtf(sut * kk);
        float t1 = 1.f / (Nn + 1e-7f);
        float nt = Nn * t1;
        float nt2 = nt * nt;
        float s = t1 * (3.4445f + nt2 * (-4.7750f + 2.0315f * nt2));
        g_ms[m] = make_float2(s, kk);
    }
}

// ================= fused scan: elementwise prep + recurrence; 4-stage cp.async =================
// thread = (d, ng of 4 states). Per window loads dt, xact hi/lo, z, knq, ms; computes
// dv/W/gate inline (same fp32 math as old prep).
__global__ __launch_bounds__(64)
void scan_kernel(const float* __restrict__ dt_bias, const float* __restrict__ Dv) {
    __shared__ __align__(16) float  s_dt[4][128];
    __shared__ __align__(16) ushort s_xh[4][128];
    __shared__ __align__(16) ushort s_xl[4][128];
    __shared__ __align__(16) float  s_z[4][128];
    __shared__ __align__(16) float  s_knq[4][384];
    __shared__ __align__(16) float2 s_ms[4][8];

    int tid = threadIdx.x;
    int ng = tid & 3, dd = tid >> 2;
    int d0 = blockIdx.x << 4;
    int d = d0 + dd;
    int b = blockIdx.y;
    size_t mbase = (size_t)b * Lz;
    const int NW = Lz / 8;

    uint32_t pdt  = (uint32_t)__cvta_generic_to_shared(s_dt);
    uint32_t pxh  = (uint32_t)__cvta_generic_to_shared(s_xh);
    uint32_t pxl  = (uint32_t)__cvta_generic_to_shared(s_xl);
    uint32_t pz   = (uint32_t)__cvta_generic_to_shared(s_z);
    uint32_t pknq = (uint32_t)__cvta_generic_to_shared(s_knq);
    uint32_t pms  = (uint32_t)__cvta_generic_to_shared(s_ms);
    const float* knq_src = g_knq + mbase * 48;

    float bias_d = dt_bias[d];
    float D_d = Dv[d];

    auto issue = [&](int w) {
        uint32_t st = (uint32_t)(w & 3);
        size_t m0 = mbase + ((size_t)w << 3);
        if (tid < 32) {
            // dt: 8 steps x 64B
            int s = tid >> 2, o = (tid & 3) << 2;
            cpa16u(pdt + st * 512 + (uint32_t)(tid << 4),
                   g_dt + (m0 + s) * DI + d0 + o);
            // z: 8 steps x 64B (from xz second half)
            cpa16u(pz + st * 512 + (uint32_t)(tid << 4),
                   g_xz + (m0 + s) * DI2 + DI + d0 + o);
        }
        if (tid < 16) {
            // xact hi/lo: 8 steps x 32B each
            int s = tid >> 1, o = (tid & 1) << 3;
            cpa16u(pxh + st * 256 + (uint32_t)(tid << 4),
                   g_xact_h + (m0 + s) * DI + d0 + o);
            cpa16u(pxl + st * 256 + (uint32_t)(tid << 4),
                   g_xact_l + (m0 + s) * DI + d0 + o);
        }
        if (tid < 4) {
            cpa16u(pms + st * 64 + (uint32_t)(tid << 4), g_ms + m0 + (tid << 1));
        }
#pragma unroll
        for (int i = 0; i < 2; i++) {
            int c = tid + (i << 6);
            if (c < 96)
                cpa16u(pknq + st * 1536 + (uint32_t)(c << 4),
                       knq_src + (((size_t)w << 3) * 48) + (c << 2));
        }
    };

    issue(0); cp_commit();
    issue(1); cp_commit();
    issue(2); cp_commit();

    float v0 = 0.f, v1 = 0.f, v2 = 0.f, v3 = 0.f;
    float h0 = 0.f, h1 = 0.f, h2 = 0.f, h3 = 0.f;

    for (int w = 0; w < NW; w++) {
        asm volatile("cp.async.wait_group 2;");
        __syncthreads();
        if (w + 3 < NW) issue(w + 3);
        cp_commit();

        int st = w & 3;
        float ys[8], xs[8];
        // phase 0: elementwise prep for the 8 steps (independent of recurrence)
        float Wv[8], dvv[8];
#pragma unroll
        for (int s = 0; s < 8; s++) {
            float2 ms = s_ms[st][s];
            float dtr = s_dt[st][(s << 4) + dd] + bias_d;
            float s0 = 1.f / (1.f + __expf(-dtr));
            float dv = s0 / (1.f + s0 * ms.y);
            float x = __bfloat162float(*reinterpret_cast<__nv_bfloat16*>(&s_xh[st][(s << 4) + dd])) +
                      __bfloat162float(*reinterpret_cast<__nv_bfloat16*>(&s_xl[st][(s << 4) + dd]));
            Wv[s] = ms.x * dv * x;
            dvv[s] = dv;
            xs[s] = x;
        }
        // phase 1: recurrence
#pragma unroll
        for (int s = 0; s < 8; s++) {
            const float* kb = &s_knq[st][s * 48 + (ng << 2)];
            float4 kv = *reinterpret_cast<const float4*>(kb);
            float4 k2 = *reinterpret_cast<const float4*>(kb + 16);
            float4 qv = *reinterpret_cast<const float4*>(kb + 32);
            v0 = fmaf(0.9f, v0, Wv[s] * kv.x); h0 = fmaf(fmaf(-dvv[s], k2.x, 1.f), h0, v0);
            v1 = fmaf(0.9f, v1, Wv[s] * kv.y); h1 = fmaf(fmaf(-dvv[s], k2.y, 1.f), h1, v1);
            v2 = fmaf(0.9f, v2, Wv[s] * kv.z); h2 = fmaf(fmaf(-dvv[s], k2.z, 1.f), h2, v2);
            v3 = fmaf(0.9f, v3, Wv[s] * kv.w); h3 = fmaf(fmaf(-dvv[s], k2.w, 1.f), h3, v3);
            ys[s] = fmaf(h0, qv.x, fmaf(h1, qv.y, fmaf(h2, qv.z, h3 * qv.w)));
        }
        // phase 2: batched cross-lane reduction + gated output
#pragma unroll
        for (int s = 0; s < 8; s++) ys[s] += __shfl_xor_sync(0xffffffffu, ys[s], 1);
#pragma unroll
        for (int s = 0; s < 8; s++) ys[s] += __shfl_xor_sync(0xffffffffu, ys[s], 2);
        if (ng == 0) {
#pragma unroll
            for (int s = 0; s < 8; s++) {
                float zv = s_z[st][(s << 4) + dd];
                float zs = zv / (1.f + __expf(-zv));
                size_t m = mbase + ((size_t)w << 3) + s;
                float yo = (ys[s] + D_d * xs[s]) * zs;
                __nv_bfloat16 h = __float2bfloat16(yo);
                g_yg_h[m * DI + d] = h;
                g_yg_l[m * DI + d] = __float2bfloat16(yo - __bfloat162float(h));
            }
        }
    }
}

// ================= launch =================
extern "C" void kernel_launch(void* const* d_in, const int* in_sizes, int n_in,
                              void* d_out, int out_size) {
    const float* hs        = (const float*)d_in[0];
    const float* in_proj_w = (const float*)d_in[1];
    const float* conv_w    = (const float*)d_in[2];
    const float* conv_b    = (const float*)d_in[3];
    const float* x_proj_w  = (const float*)d_in[4];
    const float* dt_head_w = (const float*)d_in[5];
    const float* dt_head_b = (const float*)d_in[6];
    const float* out_proj  = (const float*)d_in[7];
    const float* Dv        = (const float*)d_in[8];
    float* out = (float*)d_out;

    static bool attr_set = false;
    if (!attr_set) {
        cudaFuncSetAttribute(mma_gemm, cudaFuncAttributeMaxDynamicSharedMemorySize, 98304);
        attr_set = true;
    }
    const int SMEMB = 98304;   // 3 stages x 32KB

    void *p_xz, *p_dt, *p_xdp;
    cudaGetSymbolAddress(&p_xz, g_xz);
    cudaGetSymbolAddress(&p_dt, g_dt);
    cudaGetSymbolAddress(&p_xdp, g_xdp);
    void *hs_h, *hs_l, *ipw_h, *ipw_l, *xact_h, *xact_l, *xpw_h, *xpw_l;
    void *dtl_h, *dtl_l, *dthw_h, *dthw_l, *yg_h, *yg_l, *opw_h, *opw_l;
    cudaGetSymbolAddress(&hs_h, g_hs_h);   cudaGetSymbolAddress(&hs_l, g_hs_l);
    cudaGetSymbolAddress(&ipw_h, g_ipw_h); cudaGetSymbolAddress(&ipw_l, g_ipw_l);
    cudaGetSymbolAddress(&xact_h, g_xact_h); cudaGetSymbolAddress(&xact_l, g_xact_l);
    cudaGetSymbolAddress(&xpw_h, g_xpw_h); cudaGetSymbolAddress(&xpw_l, g_xpw_l);
    cudaGetSymbolAddress(&dtl_h, g_dtl_h); cudaGetSymbolAddress(&dtl_l, g_dtl_l);
    cudaGetSymbolAddress(&dthw_h, g_dthw_h); cudaGetSymbolAddress(&dthw_l, g_dthw_l);
    cudaGetSymbolAddress(&yg_h, g_yg_h);   cudaGetSymbolAddress(&yg_l, g_yg_l);
    cudaGetSymbolAddress(&opw_h, g_opw_h); cudaGetSymbolAddress(&opw_l, g_opw_l);

    // 0) fused splits: hs, in_proj_w, x_proj_w, out_proj, dt_head_w(pad)
    {
        int n0 = Mz * DM, n1 = DI2 * DM, n2 = XDB * DI, n3 = DM * DI, n4 = DI * RKP;
        int g0 = (n0 + 255) / 256, g1 = (n1 + 255) / 256, g2 = (n2 + 255) / 256,
            g3 = (n3 + 255) / 256, g4 = (n4 + 255) / 256;
        split5_kernel<<<g0 + g1 + g2 + g3 + g4, 256>>>(
            hs, (__nv_bfloat16*)hs_h, (__nv_bfloat16*)hs_l, n0, g0,
            in_proj_w, (__nv_bfloat16*)ipw_h, (__nv_bfloat16*)ipw_l, n1, g0 + g1,
            x_proj_w, (__nv_bfloat16*)xpw_h, (__nv_bfloat16*)xpw_l, n2, g0 + g1 + g2,
            out_proj, (__nv_bfloat16*)opw_h, (__nv_bfloat16*)opw_l, n3, g0 + g1 + g2 + g3,
            dt_head_w, (__nv_bfloat16*)dthw_h, (__nv_bfloat16*)dthw_l, n4);
    }

    // 1) xz = hs @ in_proj^T  (2048 x 3072, K=768)
    mma_gemm<<<dim3(DI2 / 128, Mz / 128, 1), 256, SMEMB>>>(
        (const __nv_bfloat16*)hs_h, (const __nv_bfloat16*)hs_l,
        (const __nv_bfloat16*)ipw_h, (const __nv_bfloat16*)ipw_l,
        (float*)p_xz, DI2, DM, DM, DI2, 0);
    // 2) conv + SiLU (bf16 hi/lo out)
    conv_silu_kernel<<<dim3(DI / 128, Lz / 16, Bz), 128>>>(conv_w, conv_b);
    // 3) x_dbl split-K partials (16-way)
    mma_gemm<<<dim3(1, Mz / 128, NSPK), 256, SMEMB>>>(
        (const __nv_bfloat16*)xact_h, (const __nv_bfloat16*)xact_l,
        (const __nv_bfloat16*)xpw_h, (const __nv_bfloat16*)xpw_l,
        (float*)p_xdp, XDB, DI / NSPK, DI, XDB, Mz * XDB);
    // 3b) reduce -> knq + dtl
    xdbl_reduce_kernel<<<(Mz * 96 + 255) / 256, 256>>>();
    // 4) dt = dt_low @ dt_head^T  (K=64 padded)
    mma_gemm<<<dim3(DI / 128, Mz / 128, 1), 256, SMEMB>>>(
        (const __nv_bfloat16*)dtl_h, (const __nv_bfloat16*)dtl_l,
        (const __nv_bfloat16*)dthw_h, (const __nv_bfloat16*)dthw_l,
        (float*)p_dt, DI, RKP, RKP, DI, 0);
    // 5) prep scalars only (s, kk per (b,t))
    prep_scalar_kernel<<<Mz, 256>>>(dt_head_b);
    // 6) fused scan
    scan_kernel<<<dim3(DI / 16, Bz), 64>>>(dt_head_b, Dv);
    // 7) out = yg @ out_proj^T
    mma_gemm<<<dim3(DM / 128, Mz / 128, 1), 256, SMEMB>>>(
        (const __nv_bfloat16*)yg_h, (const __nv_bfloat16*)yg_l,
        (const __nv_bfloat16*)opw_h, (const __nv_bfloat16*)opw_l,
        out, DM, DI, DI, DM, 0);
}

// round 14
// speedup vs baseline: 1.7922x; 1.7922x over previous
#include <cuda_runtime.h>
#include <cuda_bf16.h>
#include <cstdint>

#define Bz 2
#define Lz 1024
#define Mz (Bz*Lz)      // 2048
#define DM 768
#define DI 1536
#define DI2 3072
#define DS 16
#define RK 48
#define RKP 64
#define XDB 80
#define NSPK 16         // split-K factor for xdbl GEMM
#define LDP 36          // smem pitch in fp32 words (32 data + 4 pad)

// ---------------- fp32 scratch ----------------
__device__ __align__(16) float g_xz[Mz*DI2];
__device__ __align__(16) float g_dt[Mz*DI];
__device__ __align__(16) float g_xdp[NSPK*Mz*XDB];   // split-K partials for xdbl
__device__ float4 g_pack[Mz*DI];                     // (W, dtt, D*x, silu z)
__device__ __align__(16) float g_knq[Mz*48];
__device__ __align__(16) float g_xact[Mz*DI];        // conv+silu(x), tf32-rounded

// ---------------- tf32-rounded fp32 GEMM operands ----------------
__device__ __align__(16) float g_hs_r[Mz*DM];
__device__ __align__(16) float g_ipw_r[DI2*DM];
__device__ __align__(16) float g_xpw_r[XDB*DI];
__device__ __align__(16) float g_dtl_r[Mz*RKP];
__device__ __align__(16) float g_dthw_r[DI*RKP];
__device__ __align__(16) float g_yg[Mz*DI];
__device__ __align__(16) float g_opw_r[DM*DI];

// ---------------- helpers ----------------
__device__ __forceinline__ uint32_t f2tf32(float x) {
    uint32_t r;
    asm("cvt.rna.tf32.f32 %0, %1;" : "=r"(r) : "f"(x));
    return r;
}
__device__ __forceinline__ float tf32r(float x) { return __uint_as_float(f2tf32(x)); }

__device__ __forceinline__ void ldsm4(uint32_t& r0, uint32_t& r1, uint32_t& r2, uint32_t& r3,
                                      uint32_t saddr) {
    asm volatile("ldmatrix.sync.aligned.m8n8.x4.shared.b16 {%0,%1,%2,%3}, [%4];"
                 : "=r"(r0), "=r"(r1), "=r"(r2), "=r"(r3) : "r"(saddr));
}
__device__ __forceinline__ void mma_tf32(float* c, uint32_t a0, uint32_t a1, uint32_t a2,
                                         uint32_t a3, uint32_t b0, uint32_t b1) {
    asm volatile(
        "mma.sync.aligned.m16n8k8.row.col.f32.tf32.tf32.f32 "
        "{%0,%1,%2,%3}, {%4,%5,%6,%7}, {%8,%9}, {%0,%1,%2,%3};"
        : "+f"(c[0]), "+f"(c[1]), "+f"(c[2]), "+f"(c[3])
        : "r"(a0), "r"(a1), "r"(a2), "r"(a3), "r"(b0), "r"(b1));
}
__device__ __forceinline__ void cpa16(uint32_t dst, const void* src, uint32_t sz) {
    asm volatile("cp.async.cg.shared.global [%0], [%1], 16, %2;" :: "r"(dst), "l"(src), "r"(sz));
}
__device__ __forceinline__ void cpa16u(uint32_t dst, const void* src) {
    asm volatile("cp.async.cg.shared.global [%0], [%1], 16;" :: "r"(dst), "l"(src));
}
__device__ __forceinline__ void cp_commit() { asm volatile("cp.async.commit_group;"); }

// ================= fused tf32-round kernel (5 segments; seg 4 = pad 48->64) =================
__global__ __launch_bounds__(256)
void round5_kernel(const float* __restrict__ s0, float* __restrict__ o0, int n0, int b0,
                   const float* __restrict__ s1, float* __restrict__ o1, int n1, int b1,
                   const float* __restrict__ s2, float* __restrict__ o2, int n2, int b2,
                   const float* __restrict__ s3, float* __restrict__ o3, int n3, int b3,
                   const float* __restrict__ s4, float* __restrict__ o4, int n4) {
    int blk = blockIdx.x;
    if (blk >= b3) {
        int i = (blk - b3) * 256 + threadIdx.x;
        if (i < n4) {
            int r = i >> 6, c = i & 63;   // RKP = 64
            float v = (c < RK) ? s4[(size_t)r * RK + c] : 0.f;
            o4[i] = tf32r(v);
        }
        return;
    }
    const float* src; float* dst; int n, i;
    if (blk < b0)      { src = s0; dst = o0; n = n0; i = blk * 256 + threadIdx.x; }
    else if (blk < b1) { src = s1; dst = o1; n = n1; i = (blk - b0) * 256 + threadIdx.x; }
    else if (blk < b2) { src = s2; dst = o2; n = n2; i = (blk - b1) * 256 + threadIdx.x; }
    else               { src = s3; dst = o3; n = n3; i = (blk - b2) * 256 + threadIdx.x; }
    if (i < n) dst[i] = tf32r(src[i]);
}

// ================= tf32 3-stage pipelined GEMM: C[M,N] = A[M,K] * B[N,K]^T =================
// Operands pre-rounded to tf32. 128x128 tile, BK=32, 256 threads, padded-36 smem rows.
// Stage = A 18432B + B 18432B = 36864B; 3 stages. Fragment addressing from the verified R2 kernel.
__global__ __launch_bounds__(256, 2)
void mma_gemm(const float* __restrict__ A, const float* __restrict__ B,
              float* __restrict__ C, int N, int Kc, int Ktot, int ldc, int partStride) {
    extern __shared__ __align__(16) float smf[];
    int tid = threadIdx.x, wid = tid >> 5, lane = tid & 31;
    int row0 = blockIdx.y << 7, col0 = blockIdx.x << 7;
    int wm = (wid >> 2) << 6, wn = (wid & 3) << 5;
    int koff = blockIdx.z * Kc;
    C += (size_t)blockIdx.z * partStride;
    uint32_t sbase = (uint32_t)__cvta_generic_to_shared(smf);
    bool wActive = (col0 + wn) < N;
    int lr = lane & 7, g = lane >> 3;

    uint32_t aOff = (uint32_t)(((wm + lr + ((g & 1) << 3)) * LDP + ((g >> 1) << 2)) << 2);
    uint32_t bOff = (uint32_t)(((wn + lr + ((g >> 1) << 3)) * LDP + ((g & 1) << 2)) << 2);

    // cp.async: 1024 chunks of 16B per operand; 4 per thread
    int rs[4]; uint32_t dw[4]; int cws[4];
#pragma unroll
    for (int i = 0; i < 4; i++) {
        int c = tid + (i << 8);
        int r = c >> 3, cw = (c & 7) << 2;
        rs[i] = r; cws[i] = cw;
        dw[i] = (uint32_t)((r * LDP + cw) << 2);
    }

    float acc[4][4][4];
#pragma unroll
    for (int i = 0; i < 4; i++)
#pragma unroll
        for (int j = 0; j < 4; j++)
#pragma unroll
            for (int r = 0; r < 4; r++) acc[i][j][r] = 0.f;

    int niter = Kc >> 5;

    auto issue = [&](int s) {
        uint32_t sb = sbase + (uint32_t)((s % 3) * 36864);
        int k0 = koff + (s << 5);
#pragma unroll
        for (int i = 0; i < 4; i++) {
            int r = rs[i], cw = cws[i];
            cpa16(sb + dw[i], A + (size_t)(row0 + r) * Ktot + k0 + cw, 16);
            int brow = col0 + r;
            uint32_t bsz = (brow < N) ? 16u : 0u;
            cpa16(sb + 18432 + dw[i],
                  B + (size_t)(brow < N ? brow : 0) * Ktot + k0 + cw, bsz);
        }
    };

    issue(0); cp_commit();
    if (niter > 1) { issue(1); cp_commit(); }

    for (int it = 0; it < niter; it++) {
        if (it + 1 < niter) asm volatile("cp.async.wait_group 1;");
        else                asm volatile("cp.async.wait_group 0;");
        __syncthreads();
        if (it + 2 < niter) { issue(it + 2); cp_commit(); }

        if (wActive) {
            uint32_t stg = sbase + (uint32_t)((it % 3) * 36864);
            uint32_t aB = stg + aOff;
            uint32_t bB = stg + 18432 + bOff;
#pragma unroll
            for (int kk = 0; kk < 4; kk++) {
                uint32_t kOff = (uint32_t)((kk << 3) << 2);
                uint32_t a[4][4], bf[2][4];
#pragma unroll
                for (int mt = 0; mt < 4; mt++)
                    ldsm4(a[mt][0], a[mt][1], a[mt][2], a[mt][3],
                          aB + (uint32_t)(((mt << 4) * LDP) << 2) + kOff);
#pragma unroll
                for (int g2 = 0; g2 < 2; g2++)
                    ldsm4(bf[g2][0], bf[g2][1], bf[g2][2], bf[g2][3],
                          bB + (uint32_t)(((g2 << 4) * LDP) << 2) + kOff);
#pragma unroll
                for (int mt = 0; mt < 4; mt++)
#pragma unroll
                    for (int nt = 0; nt < 4; nt++) {
                        uint32_t b0 = bf[nt >> 1][(nt & 1) << 1];
                        uint32_t b1 = bf[nt >> 1][((nt & 1) << 1) + 1];
                        mma_tf32(acc[mt][nt], a[mt][0], a[mt][1], a[mt][2], a[mt][3], b0, b1);
                    }
            }
        }
    }

    int cr = lane >> 2, cc = (lane & 3) << 1;
#pragma unroll
    for (int mt = 0; mt < 4; mt++)
#pragma unroll
        for (int nt = 0; nt < 4; nt++) {
            int row = row0 + wm + (mt << 4) + cr;
            int col = col0 + wn + (nt << 3) + cc;
            if (col < N) {
                *reinterpret_cast<float2*>(C + (size_t)row * ldc + col) =
                    make_float2(acc[mt][nt][0], acc[mt][nt][1]);
                *reinterpret_cast<float2*>(C + (size_t)(row + 8) * ldc + col) =
                    make_float2(acc[mt][nt][2], acc[mt][nt][3]);
            }
        }
}

// ================= xdbl split-K reduce + scatter (knq + dtl round/pad) =================
__global__ __launch_bounds__(256)
void xdbl_reduce_kernel() {
    int i = blockIdx.x * 256 + threadIdx.x;
    if (i >= Mz * 96) return;
    int r = i / 96, c = i - r * 96;
    if (c < 48) {
        float v = 0.f;
#pragma unroll
        for (int z = 0; z < NSPK; z++) v += g_xdp[(size_t)z * Mz * XDB + (size_t)r * XDB + c];
        g_dtl_r[(size_t)r * RKP + c] = tf32r(v);
    } else if (c < 64) {
        g_dtl_r[(size_t)r * RKP + c] = 0.f;
    } else if (c < 80) {
        int sc = c - 16;
        float v = 0.f;
#pragma unroll
        for (int z = 0; z < NSPK; z++) v += g_xdp[(size_t)z * Mz * XDB + (size_t)r * XDB + sc];
        g_knq[(size_t)r * 48 + (c - 64)] = v;
        g_knq[(size_t)r * 48 + 16 + (c - 64)] = v * v;
    } else {
        int sc = c - 16;
        float v = 0.f;
#pragma unroll
        for (int z = 0; z < NSPK; z++) v += g_xdp[(size_t)z * Mz * XDB + (size_t)r * XDB + sc];
        g_knq[(size_t)r * 48 + 32 + (c - 80)] = v;
    }
}

// ================= depthwise causal conv (k=4) + SiLU -> tf32-rounded fp32 =================
__global__ __launch_bounds__(128)
void conv_silu_kernel(const float* __restrict__ conv_w,
                      const float* __restrict__ conv_b) {
    int d = blockIdx.x * 128 + threadIdx.x;
    int t0 = blockIdx.y * 16;
    int b = blockIdx.z;
    size_t base = (size_t)b * Lz;

    float xv[19];
#pragma unroll
    for (int i = 0; i < 19; i++) {
        int t = t0 - 3 + i;
        xv[i] = (t >= 0) ? g_xz[(base + t) * DI2 + d] : 0.f;
    }
    float w0 = conv_w[d * 4 + 0], w1 = conv_w[d * 4 + 1];
    float w2 = conv_w[d * 4 + 2], w3 = conv_w[d * 4 + 3];
    float bias = conv_b[d];
#pragma unroll
    for (int j = 0; j < 16; j++) {
        float a = fmaf(w0, xv[j], fmaf(w1, xv[j + 1], fmaf(w2, xv[j + 2], fmaf(w3, xv[j + 3], bias))));
        float s = a / (1.f + __expf(-a));
        g_xact[(base + t0 + j) * DI + d] = tf32r(s);
    }
}

// ================= prep: rank-1 Newton-Schulz closed form + fp32 pack =================
__global__ __launch_bounds__(256)
void prep_kernel(const float* __restrict__ dt_bias, const float* __restrict__ Dv) {
    int m = blockIdx.x;
    int tid = threadIdx.x;
    __shared__ float s_ksq[16];
    __shared__ float s_kk, s_su;
    __shared__ float red[8];

    if (tid < 16) s_ksq[tid] = g_knq[(size_t)m * 48 + 16 + tid];
    __syncthreads();
    if (tid == 0) {
        float kk = 0.f;
#pragma unroll
        for (int n = 0; n < 16; n++) kk += s_ksq[n];
        s_kk = kk;
    }
    __syncthreads();
    float kk = s_kk;

    float u[6], dtt[6], xv[6];
    float su = 0.f;
#pragma unroll
    for (int i = 0; i < 6; i++) {
        int d = tid + i * 256;
        float dtr = g_dt[(size_t)m * DI + d] + dt_bias[d];
        float s0 = 1.f / (1.f + __expf(-dtr));
        float dv = s0 / (1.f + s0 * kk);
        float x = g_xact[(size_t)m * DI + d];
        float uu = dv * x;
        su += uu * uu;
        u[i] = uu; dtt[i] = dv; xv[i] = x;
    }
#pragma unroll
    for (int off = 16; off > 0; off >>= 1) su += __shfl_xor_sync(0xffffffffu, su, off);
    if ((tid & 31) == 0) red[tid >> 5] = su;
    __syncthreads();
    if (tid == 0) {
        float s = 0.f;
#pragma unroll
        for (int i = 0; i < 8; i++) s += red[i];
        s_su = s;
    }
    __syncthreads();

    float Nn = sqrtf(s_su * kk);
    float t1 = 1.f / (Nn + 1e-7f);
    float nt = Nn * t1;
    float nt2 = nt * nt;
    float s = t1 * (3.4445f + nt2 * (-4.7750f + 2.0315f * nt2));

#pragma unroll
    for (int i = 0; i < 6; i++) {
        int d = tid + i * 256;
        float z = g_xz[(size_t)m * DI2 + DI + d];
        float zs = z / (1.f + __expf(-z));
        g_pack[(size_t)m * DI + d] = make_float4(s * u[i], dtt[i], Dv[d] * xv[i], zs);
    }
}

// ================= scan: 4-way n-split; 4-stage cp.async; tf32-rounded yg =================
__global__ __launch_bounds__(64)
void scan_kernel() {
    __shared__ __align__(16) float4 s_pack[4][128];
    __shared__ __align__(16) float  s_knq[4][384];
    int tid = threadIdx.x;
    int ng = tid & 3, dd = tid >> 2;
    int d0 = blockIdx.x << 4;
    int d = d0 + dd;
    int b = blockIdx.y;
    size_t mbase = (size_t)b * Lz;
    const int NW = Lz / 8;

    uint32_t spack = (uint32_t)__cvta_generic_to_shared(s_pack);
    uint32_t sknq  = (uint32_t)__cvta_generic_to_shared(s_knq);
    const float* knq_src = g_knq + mbase * 48;

    auto issue = [&](int w) {
        uint32_t st = (uint32_t)(w & 3);
#pragma unroll
        for (int i = 0; i < 2; i++) {
            int c = tid + (i << 6);
            int s = c >> 4, dd2 = c & 15;
            const float4* src = &g_pack[(mbase + ((size_t)w << 3) + s) * DI + d0 + dd2];
            cpa16u(spack + st * 2048 + (uint32_t)(c << 4), src);
        }
#pragma unroll
        for (int i = 0; i < 2; i++) {
            int c = tid + (i << 6);
            if (c < 96) {
                const float* src = knq_src + (((size_t)w << 3) * 48) + (c << 2);
                cpa16u(sknq + st * 1536 + (uint32_t)(c << 4), src);
            }
        }
    };

    issue(0); cp_commit();
    issue(1); cp_commit();
    issue(2); cp_commit();

    float v0 = 0.f, v1 = 0.f, v2 = 0.f, v3 = 0.f;
    float h0 = 0.f, h1 = 0.f, h2 = 0.f, h3 = 0.f;

    for (int w = 0; w < NW; w++) {
        asm volatile("cp.async.wait_group 2;");
        __syncthreads();
        if (w + 3 < NW) issue(w + 3);
        cp_commit();

        int st = w & 3;
        float ys[8];
#pragma unroll
        for (int s = 0; s < 8; s++) {
            float4 p = s_pack[st][(s << 4) + dd];
            const float* kb = &s_knq[st][s * 48 + (ng << 2)];
            float4 kv = *reinterpret_cast<const float4*>(kb);
            float4 k2 = *reinterpret_cast<const float4*>(kb + 16);
            float4 qv = *reinterpret_cast<const float4*>(kb + 32);
            v0 = fmaf(0.9f, v0, p.x * kv.x); h0 = fmaf(fmaf(-p.y, k2.x, 1.f), h0, v0);
            v1 = fmaf(0.9f, v1, p.x * kv.y); h1 = fmaf(fmaf(-p.y, k2.y, 1.f), h1, v1);
            v2 = fmaf(0.9f, v2, p.x * kv.z); h2 = fmaf(fmaf(-p.y, k2.z, 1.f), h2, v2);
            v3 = fmaf(0.9f, v3, p.x * kv.w); h3 = fmaf(fmaf(-p.y, k2.w, 1.f), h3, v3);
            ys[s] = fmaf(h0, qv.x, fmaf(h1, qv.y, fmaf(h2, qv.z, h3 * qv.w)));
        }
#pragma unroll
        for (int s = 0; s < 8; s++) ys[s] += __shfl_xor_sync(0xffffffffu, ys[s], 1);
#pragma unroll
        for (int s = 0; s < 8; s++) ys[s] += __shfl_xor_sync(0xffffffffu, ys[s], 2);
        if (ng == 0) {
#pragma unroll
            for (int s = 0; s < 8; s++) {
                float4 p = s_pack[st][(s << 4) + dd];
                size_t m = mbase + ((size_t)w << 3) + s;
                float yo = (ys[s] + p.z) * p.w;
                g_yg[m * DI + d] = tf32r(yo);
            }
        }
    }
}

// ================= launch =================
extern "C" void kernel_launch(void* const* d_in, const int* in_sizes, int n_in,
                              void* d_out, int out_size) {
    const float* hs        = (const float*)d_in[0];
    const float* in_proj_w = (const float*)d_in[1];
    const float* conv_w    = (const float*)d_in[2];
    const float* conv_b    = (const float*)d_in[3];
    const float* x_proj_w  = (const float*)d_in[4];
    const float* dt_head_w = (const float*)d_in[5];
    const float* dt_head_b = (const float*)d_in[6];
    const float* out_proj  = (const float*)d_in[7];
    const float* Dv        = (const float*)d_in[8];
    float* out = (float*)d_out;

    static bool attr_set = false;
    if (!attr_set) {
        cudaFuncSetAttribute(mma_gemm, cudaFuncAttributeMaxDynamicSharedMemorySize, 110592);
        attr_set = true;
    }
    const int SMEMB = 110592;   // 3 stages x 36864B

    void *p_xz, *p_dt, *p_xdp, *p_xact, *p_yg;
    cudaGetSymbolAddress(&p_xz, g_xz);
    cudaGetSymbolAddress(&p_dt, g_dt);
    cudaGetSymbolAddress(&p_xdp, g_xdp);
    cudaGetSymbolAddress(&p_xact, g_xact);
    cudaGetSymbolAddress(&p_yg, g_yg);
    void *hs_r, *ipw_r, *xpw_r, *dtl_r, *dthw_r, *opw_r;
    cudaGetSymbolAddress(&hs_r, g_hs_r);
    cudaGetSymbolAddress(&ipw_r, g_ipw_r);
    cudaGetSymbolAddress(&xpw_r, g_xpw_r);
    cudaGetSymbolAddress(&dtl_r, g_dtl_r);
    cudaGetSymbolAddress(&dthw_r, g_dthw_r);
    cudaGetSymbolAddress(&opw_r, g_opw_r);

    // 0) fused tf32-round: hs, in_proj_w, x_proj_w, out_proj, dt_head_w(pad)
    {
        int n0 = Mz * DM, n1 = DI2 * DM, n2 = XDB * DI, n3 = DM * DI, n4 = DI * RKP;
        int g0 = (n0 + 255) / 256, g1 = (n1 + 255) / 256, g2 = (n2 + 255) / 256,
            g3 = (n3 + 255) / 256, g4 = (n4 + 255) / 256;
        round5_kernel<<<g0 + g1 + g2 + g3 + g4, 256>>>(
            hs, (float*)hs_r, n0, g0,
            in_proj_w, (float*)ipw_r, n1, g0 + g1,
            x_proj_w, (float*)xpw_r, n2, g0 + g1 + g2,
            out_proj, (float*)opw_r, n3, g0 + g1 + g2 + g3,
            dt_head_w, (float*)dthw_r, n4);
    }

    // 1) xz = hs @ in_proj^T  (2048 x 3072, K=768)
    mma_gemm<<<dim3(DI2 / 128, Mz / 128, 1), 256, SMEMB>>>(
        (const float*)hs_r, (const float*)ipw_r, (float*)p_xz, DI2, DM, DM, DI2, 0);
    // 2) conv + SiLU (tf32-rounded fp32 out)
    conv_silu_kernel<<<dim3(DI / 128, Lz / 16, Bz), 128>>>(conv_w, conv_b);
    // 3) x_dbl split-K partials (16-way, Kc=96)
    mma_gemm<<<dim3(1, Mz / 128, NSPK), 256, SMEMB>>>(
        (const float*)p_xact, (const float*)xpw_r, (float*)p_xdp,
        XDB, DI / NSPK, DI, XDB, Mz * XDB);
    // 3b) reduce -> knq + dtl (round/pad)
    xdbl_reduce_kernel<<<(Mz * 96 + 255) / 256, 256>>>();
    // 4) dt = dt_low @ dt_head^T  (K=64 padded)
    mma_gemm<<<dim3(DI / 128, Mz / 128, 1), 256, SMEMB>>>(
        (const float*)dtl_r, (const float*)dthw_r, (float*)p_dt, DI, RKP, RKP, DI, 0);
    // 5) prep (fp32 pack)
    prep_kernel<<<Mz, 256>>>(dt_head_b, Dv);
    // 6) scan
    scan_kernel<<<dim3(DI / 16, Bz), 64>>>();
    // 7) out = yg @ out_proj^T
    mma_gemm<<<dim3(DM / 128, Mz / 128, 1), 256, SMEMB>>>(
        (const float*)p_yg, (const float*)opw_r, out, DM, DI, DI, DM, 0);
}

// round 15
// speedup vs baseline: 2.3845x; 1.3305x over previous
#include <cuda_runtime.h>
#include <cuda_fp16.h>
#include <cstdint>

#define Bz 2
#define Lz 1024
#define Mz (Bz*Lz)      // 2048
#define DM 768
#define DI 1536
#define DI2 3072
#define DS 16
#define RK 48
#define RKP 64
#define XDB 80
#define NSPK 16         // split-K factor for xdbl GEMM

// ---------------- fp32 scratch ----------------
__device__ __align__(16) float g_xz[Mz*DI2];
__device__ __align__(16) float g_dt[Mz*DI];
__device__ __align__(16) float g_xdp[NSPK*Mz*XDB];   // split-K partials for xdbl
__device__ float4 g_pack[Mz*DI];                     // (W, dtt, D*x, silu z)
__device__ __align__(16) float g_knq[Mz*48];
__device__ __align__(16) float g_xact[Mz*DI];        // conv+silu(x), fp32 (for prep)

// ---------------- fp16 GEMM operands ----------------
__device__ __align__(16) __half g_hs_c[Mz*DM];
__device__ __align__(16) __half g_ipw_c[DI2*DM];
__device__ __align__(16) __half g_xact_c[Mz*DI];
__device__ __align__(16) __half g_xpw_c[XDB*DI];
__device__ __align__(16) __half g_dtl_c[Mz*RKP];
__device__ __align__(16) __half g_dthw_c[DI*RKP];
__device__ __align__(16) __half g_yg_c[Mz*DI];
__device__ __align__(16) __half g_opw_c[DM*DI];

// ---------------- helpers ----------------
__device__ __forceinline__ void ldsm4(uint32_t& r0, uint32_t& r1, uint32_t& r2, uint32_t& r3,
                                      uint32_t saddr) {
    asm volatile("ldmatrix.sync.aligned.m8n8.x4.shared.b16 {%0,%1,%2,%3}, [%4];"
                 : "=r"(r0), "=r"(r1), "=r"(r2), "=r"(r3) : "r"(saddr));
}
__device__ __forceinline__ void mma_f16(float* c, const uint32_t* a, const uint32_t* b) {
    asm volatile(
        "mma.sync.aligned.m16n8k16.row.col.f32.f16.f16.f32 "
        "{%0,%1,%2,%3}, {%4,%5,%6,%7}, {%8,%9}, {%0,%1,%2,%3};"
        : "+f"(c[0]), "+f"(c[1]), "+f"(c[2]), "+f"(c[3])
        : "r"(a[0]), "r"(a[1]), "r"(a[2]), "r"(a[3]), "r"(b[0]), "r"(b[1]));
}
__device__ __forceinline__ void cpa16(uint32_t dst, const void* src, uint32_t sz) {
    asm volatile("cp.async.cg.shared.global [%0], [%1], 16, %2;" :: "r"(dst), "l"(src), "r"(sz));
}
__device__ __forceinline__ void cpa16u(uint32_t dst, const void* src) {
    asm volatile("cp.async.cg.shared.global [%0], [%1], 16;" :: "r"(dst), "l"(src));
}
__device__ __forceinline__ void cp_commit() { asm volatile("cp.async.commit_group;"); }

// ================= fused fp16-convert kernel (5 segments; seg 4 = pad 48->64) =================
__global__ __launch_bounds__(256)
void cvt5_kernel(const float* __restrict__ s0, __half* __restrict__ o0, int n0, int b0,
                 const float* __restrict__ s1, __half* __restrict__ o1, int n1, int b1,
                 const float* __restrict__ s2, __half* __restrict__ o2, int n2, int b2,
                 const float* __restrict__ s3, __half* __restrict__ o3, int n3, int b3,
                 const float* __restrict__ s4, __half* __restrict__ o4, int n4) {
    int blk = blockIdx.x;
    if (blk >= b3) {
        int i = (blk - b3) * 256 + threadIdx.x;
        if (i < n4) {
            int r = i >> 6, c = i & 63;   // RKP = 64
            float v = (c < RK) ? s4[(size_t)r * RK + c] : 0.f;
            o4[i] = __float2half_rn(v);
        }
        return;
    }
    const float* src; __half* dst; int n, i;
    if (blk < b0)      { src = s0; dst = o0; n = n0; i = blk * 256 + threadIdx.x; }
    else if (blk < b1) { src = s1; dst = o1; n = n1; i = (blk - b0) * 256 + threadIdx.x; }
    else if (blk < b2) { src = s2; dst = o2; n = n2; i = (blk - b1) * 256 + threadIdx.x; }
    else               { src = s3; dst = o3; n = n3; i = (blk - b2) * 256 + threadIdx.x; }
    if (i < n) dst[i] = __float2half_rn(src[i]);
}

// ================= fp16 3-stage swizzled GEMM: C[M,N] = A[M,K] * B[N,K]^T =================
// Single fp16 MMA per K=16. 128x128 tile, BK=32, XOR-swizzled 64B rows.
// Stage = A 8KB | B 8KB = 16KB; 3 stages. Safe single-barrier pipeline (R9-verified).
__global__ __launch_bounds__(256, 2)
void mma_gemm(const __half* __restrict__ A, const __half* __restrict__ B,
              float* __restrict__ C, int N, int Kc, int Ktot, int ldc, int partStride) {
    extern __shared__ __align__(16) ushort smbuf[];
    int tid = threadIdx.x, wid = tid >> 5, lane = tid & 31;
    int row0 = blockIdx.y << 7, col0 = blockIdx.x << 7;
    int wm = (wid >> 2) << 6, wn = (wid & 3) << 5;
    int koff = blockIdx.z * Kc;
    C += (size_t)blockIdx.z * partStride;
    uint32_t sbase = (uint32_t)__cvta_generic_to_shared(smbuf);
    bool wActive = (col0 + wn) < N;

    int c0 = tid, c1 = tid + 256;
    int r0 = c0 >> 2, ch0 = c0 & 3, o0 = ch0 << 3;
    int r1 = c1 >> 2, ch1 = c1 & 3, o1 = ch1 << 3;
    int br0 = col0 + r0, br1 = col0 + r1;
    uint32_t s0 = br0 < N ? 16u : 0u, s1 = br1 < N ? 16u : 0u;
    size_t a0b = (size_t)(row0 + r0) * Ktot + koff + o0;
    size_t a1b = (size_t)(row0 + r1) * Ktot + koff + o1;
    size_t b0b = (size_t)(br0 < N ? br0 : 0) * Ktot + koff + o0;
    size_t b1b = (size_t)(br1 < N ? br1 : 0) * Ktot + koff + o1;
    uint32_t d0 = (uint32_t)(r0 * 64 + ((ch0 ^ ((r0 >> 1) & 3)) << 4));
    uint32_t d1 = (uint32_t)(r1 * 64 + ((ch1 ^ ((r1 >> 1) & 3)) << 4));

    uint32_t swa = (uint32_t)(((lane & 15) >> 1) & 3);
    uint32_t cgA = (uint32_t)(lane >> 4);
    uint32_t aRow = (uint32_t)((wm + (lane & 15)) * 64);
    uint32_t swb = (uint32_t)(((lane & 7) >> 1) & 3);
    uint32_t cgB = (uint32_t)((lane >> 3) & 1);
    uint32_t bRow = (uint32_t)((wn + ((lane >> 4) << 3) + (lane & 7)) * 64);

    float acc[4][4][4];
#pragma unroll
    for (int i = 0; i < 4; i++)
#pragma unroll
        for (int j = 0; j < 4; j++)
#pragma unroll
            for (int r = 0; r < 4; r++) acc[i][j][r] = 0.f;

    int niter = Kc >> 5;

    auto issue = [&](int s) {
        uint32_t sb = sbase + (uint32_t)((s % 3) * 16384);
        int ko = s << 5;
        cpa16(sb + d0,        A + a0b + ko, 16);
        cpa16(sb + d1,        A + a1b + ko, 16);
        cpa16(sb + 8192 + d0, B + b0b + ko, s0);
        cpa16(sb + 8192 + d1, B + b1b + ko, s1);
    };

    issue(0); cp_commit();
    if (niter > 1) { issue(1); cp_commit(); }

    for (int it = 0; it < niter; it++) {
        if (it + 1 < niter) asm volatile("cp.async.wait_group 1;");
        else                asm volatile("cp.async.wait_group 0;");
        __syncthreads();
        if (it + 2 < niter) { issue(it + 2); cp_commit(); }

        if (wActive) {
            uint32_t stg = sbase + (uint32_t)((it % 3) * 16384);
#pragma unroll
            for (int kk = 0; kk < 2; kk++) {
                uint32_t ca = ((((uint32_t)(kk << 1) + cgA) ^ swa) << 4);
                uint32_t cb = ((((uint32_t)(kk << 1) + cgB) ^ swb) << 4);
                uint32_t a[4][4], bf[4][2];
#pragma unroll
                for (int mt = 0; mt < 4; mt++)
                    ldsm4(a[mt][0], a[mt][1], a[mt][2], a[mt][3],
                          stg + aRow + (uint32_t)(mt * 1024) + ca);
#pragma unroll
                for (int g = 0; g < 2; g++) {
                    uint32_t q0, q1, q2, q3;
                    ldsm4(q0, q1, q2, q3, stg + 8192 + bRow + (uint32_t)(g * 1024) + cb);
                    bf[2 * g][0] = q0; bf[2 * g][1] = q1;
                    bf[2 * g + 1][0] = q2; bf[2 * g + 1][1] = q3;
                }
#pragma unroll
                for (int mt = 0; mt < 4; mt++)
#pragma unroll
                    for (int ng = 0; ng < 4; ng++) mma_f16(acc[mt][ng], a[mt], bf[ng]);
            }
        }
    }

    int cr = lane >> 2, cc = (lane & 3) << 1;
#pragma unroll
    for (int mt = 0; mt < 4; mt++)
#pragma unroll
        for (int ng = 0; ng < 4; ng++) {
            int row = row0 + wm + (mt << 4) + cr;
            int col = col0 + wn + (ng << 3) + cc;
            if (col < N) {
                *reinterpret_cast<float2*>(C + (size_t)row * ldc + col) =
                    make_float2(acc[mt][ng][0], acc[mt][ng][1]);
                *reinterpret_cast<float2*>(C + (size_t)(row + 8) * ldc + col) =
                    make_float2(acc[mt][ng][2], acc[mt][ng][3]);
            }
        }
}

// ================= xdbl split-K reduce + scatter (knq + dtl convert/pad) =================
__global__ __launch_bounds__(256)
void xdbl_reduce_kernel() {
    int i = blockIdx.x * 256 + threadIdx.x;
    if (i >= Mz * 96) return;
    int r = i / 96, c = i - r * 96;
    if (c < 48) {
        float v = 0.f;
#pragma unroll
        for (int z = 0; z < NSPK; z++) v += g_xdp[(size_t)z * Mz * XDB + (size_t)r * XDB + c];
        g_dtl_c[(size_t)r * RKP + c] = __float2half_rn(v);
    } else if (c < 64) {
        g_dtl_c[(size_t)r * RKP + c] = __float2half_rn(0.f);
    } else if (c < 80) {
        int sc = c - 16;
        float v = 0.f;
#pragma unroll
        for (int z = 0; z < NSPK; z++) v += g_xdp[(size_t)z * Mz * XDB + (size_t)r * XDB + sc];
        g_knq[(size_t)r * 48 + (c - 64)] = v;
        g_knq[(size_t)r * 48 + 16 + (c - 64)] = v * v;
    } else {
        int sc = c - 16;
        float v = 0.f;
#pragma unroll
        for (int z = 0; z < NSPK; z++) v += g_xdp[(size_t)z * Mz * XDB + (size_t)r * XDB + sc];
        g_knq[(size_t)r * 48 + 32 + (c - 80)] = v;
    }
}

// ================= depthwise causal conv (k=4) + SiLU -> fp32 + fp16 =================
__global__ __launch_bounds__(128)
void conv_silu_kernel(const float* __restrict__ conv_w,
                      const float* __restrict__ conv_b) {
    int d = blockIdx.x * 128 + threadIdx.x;
    int t0 = blockIdx.y * 16;
    int b = blockIdx.z;
    size_t base = (size_t)b * Lz;

    float xv[19];
#pragma unroll
    for (int i = 0; i < 19; i++) {
        int t = t0 - 3 + i;
        xv[i] = (t >= 0) ? g_xz[(base + t) * DI2 + d] : 0.f;
    }
    float w0 = conv_w[d * 4 + 0], w1 = conv_w[d * 4 + 1];
    float w2 = conv_w[d * 4 + 2], w3 = conv_w[d * 4 + 3];
    float bias = conv_b[d];
#pragma unroll
    for (int j = 0; j < 16; j++) {
        float a = fmaf(w0, xv[j], fmaf(w1, xv[j + 1], fmaf(w2, xv[j + 2], fmaf(w3, xv[j + 3], bias))));
        float s = a / (1.f + __expf(-a));
        size_t idx = (base + t0 + j) * DI + d;
        g_xact[idx] = s;
        g_xact_c[idx] = __float2half_rn(s);
    }
}

// ================= prep: rank-1 Newton-Schulz closed form + fp32 pack =================
__global__ __launch_bounds__(256)
void prep_kernel(const float* __restrict__ dt_bias, const float* __restrict__ Dv) {
    int m = blockIdx.x;
    int tid = threadIdx.x;
    __shared__ float s_ksq[16];
    __shared__ float s_kk, s_su;
    __shared__ float red[8];

    if (tid < 16) s_ksq[tid] = g_knq[(size_t)m * 48 + 16 + tid];
    __syncthreads();
    if (tid == 0) {
        float kk = 0.f;
#pragma unroll
        for (int n = 0; n < 16; n++) kk += s_ksq[n];
        s_kk = kk;
    }
    __syncthreads();
    float kk = s_kk;

    float u[6], dtt[6], xv[6];
    float su = 0.f;
#pragma unroll
    for (int i = 0; i < 6; i++) {
        int d = tid + i * 256;
        float dtr = g_dt[(size_t)m * DI + d] + dt_bias[d];
        float s0 = 1.f / (1.f + __expf(-dtr));
        float dv = s0 / (1.f + s0 * kk);
        float x = g_xact[(size_t)m * DI + d];
        float uu = dv * x;
        su += uu * uu;
        u[i] = uu; dtt[i] = dv; xv[i] = x;
    }
#pragma unroll
    for (int off = 16; off > 0; off >>= 1) su += __shfl_xor_sync(0xffffffffu, su, off);
    if ((tid & 31) == 0) red[tid >> 5] = su;
    __syncthreads();
    if (tid == 0) {
        float s = 0.f;
#pragma unroll
        for (int i = 0; i < 8; i++) s += red[i];
        s_su = s;
    }
    __syncthreads();

    float Nn = sqrtf(s_su * kk);
    float t1 = 1.f / (Nn + 1e-7f);
    float nt = Nn * t1;
    float nt2 = nt * nt;
    float s = t1 * (3.4445f + nt2 * (-4.7750f + 2.0315f * nt2));

#pragma unroll
    for (int i = 0; i < 6; i++) {
        int d = tid + i * 256;
        float z = g_xz[(size_t)m * DI2 + DI + d];
        float zs = z / (1.f + __expf(-z));
        g_pack[(size_t)m * DI + d] = make_float4(s * u[i], dtt[i], Dv[d] * xv[i], zs);
    }
}

// ================= scan: 4-way n-split; 4-stage cp.async; fp16 yg out =================
__global__ __launch_bounds__(64)
void scan_kernel() {
    __shared__ __align__(16) float4 s_pack[4][128];
    __shared__ __align__(16) float  s_knq[4][384];
    int tid = threadIdx.x;
    int ng = tid & 3, dd = tid >> 2;
    int d0 = blockIdx.x << 4;
    int d = d0 + dd;
    int b = blockIdx.y;
    size_t mbase = (size_t)b * Lz;
    const int NW = Lz / 8;

    uint32_t spack = (uint32_t)__cvta_generic_to_shared(s_pack);
    uint32_t sknq  = (uint32_t)__cvta_generic_to_shared(s_knq);
    const float* knq_src = g_knq + mbase * 48;

    auto issue = [&](int w) {
        uint32_t st = (uint32_t)(w & 3);
#pragma unroll
        for (int i = 0; i < 2; i++) {
            int c = tid + (i << 6);
            int s = c >> 4, dd2 = c & 15;
            const float4* src = &g_pack[(mbase + ((size_t)w << 3) + s) * DI + d0 + dd2];
            cpa16u(spack + st * 2048 + (uint32_t)(c << 4), src);
        }
#pragma unroll
        for (int i = 0; i < 2; i++) {
            int c = tid + (i << 6);
            if (c < 96) {
                const float* src = knq_src + (((size_t)w << 3) * 48) + (c << 2);
                cpa16u(sknq + st * 1536 + (uint32_t)(c << 4), src);
            }
        }
    };

    issue(0); cp_commit();
    issue(1); cp_commit();
    issue(2); cp_commit();

    float v0 = 0.f, v1 = 0.f, v2 = 0.f, v3 = 0.f;
    float h0 = 0.f, h1 = 0.f, h2 = 0.f, h3 = 0.f;

    for (int w = 0; w < NW; w++) {
        asm volatile("cp.async.wait_group 2;");
        __syncthreads();
        if (w + 3 < NW) issue(w + 3);
        cp_commit();

        int st = w & 3;
        float ys[8];
#pragma unroll
        for (int s = 0; s < 8; s++) {
            float4 p = s_pack[st][(s << 4) + dd];
            const float* kb = &s_knq[st][s * 48 + (ng << 2)];
            float4 kv = *reinterpret_cast<const float4*>(kb);
            float4 k2 = *reinterpret_cast<const float4*>(kb + 16);
            float4 qv = *reinterpret_cast<const float4*>(kb + 32);
            v0 = fmaf(0.9f, v0, p.x * kv.x); h0 = fmaf(fmaf(-p.y, k2.x, 1.f), h0, v0);
            v1 = fmaf(0.9f, v1, p.x * kv.y); h1 = fmaf(fmaf(-p.y, k2.y, 1.f), h1, v1);
            v2 = fmaf(0.9f, v2, p.x * kv.z); h2 = fmaf(fmaf(-p.y, k2.z, 1.f), h2, v2);
            v3 = fmaf(0.9f, v3, p.x * kv.w); h3 = fmaf(fmaf(-p.y, k2.w, 1.f), h3, v3);
            ys[s] = fmaf(h0, qv.x, fmaf(h1, qv.y, fmaf(h2, qv.z, h3 * qv.w)));
        }
#pragma unroll
        for (int s = 0; s < 8; s++) ys[s] += __shfl_xor_sync(0xffffffffu, ys[s], 1);
#pragma unroll
        for (int s = 0; s < 8; s++) ys[s] += __shfl_xor_sync(0xffffffffu, ys[s], 2);
        if (ng == 0) {
#pragma unroll
            for (int s = 0; s < 8; s++) {
                float4 p = s_pack[st][(s << 4) + dd];
                size_t m = mbase + ((size_t)w << 3) + s;
                float yo = (ys[s] + p.z) * p.w;
                g_yg_c[m * DI + d] = __float2half_rn(yo);
            }
        }
    }
}

// ================= launch =================
extern "C" void kernel_launch(void* const* d_in, const int* in_sizes, int n_in,
                              void* d_out, int out_size) {
    const float* hs        = (const float*)d_in[0];
    const float* in_proj_w = (const float*)d_in[1];
    const float* conv_w    = (const float*)d_in[2];
    const float* conv_b    = (const float*)d_in[3];
    const float* x_proj_w  = (const float*)d_in[4];
    const float* dt_head_w = (const float*)d_in[5];
    const float* dt_head_b = (const float*)d_in[6];
    const float* out_proj  = (const float*)d_in[7];
    const float* Dv        = (const float*)d_in[8];
    float* out = (float*)d_out;

    static bool attr_set = false;
    if (!attr_set) {
        cudaFuncSetAttribute(mma_gemm, cudaFuncAttributeMaxDynamicSharedMemorySize, 49152);
        attr_set = true;
    }
    const int SMEMB = 49152;   // 3 stages x 16KB

    void *p_xz, *p_dt, *p_xdp;
    cudaGetSymbolAddress(&p_xz, g_xz);
    cudaGetSymbolAddress(&p_dt, g_dt);
    cudaGetSymbolAddress(&p_xdp, g_xdp);
    void *hs_c, *ipw_c, *xact_c, *xpw_c, *dtl_c, *dthw_c, *yg_c, *opw_c;
    cudaGetSymbolAddress(&hs_c, g_hs_c);
    cudaGetSymbolAddress(&ipw_c, g_ipw_c);
    cudaGetSymbolAddress(&xact_c, g_xact_c);
    cudaGetSymbolAddress(&xpw_c, g_xpw_c);
    cudaGetSymbolAddress(&dtl_c, g_dtl_c);
    cudaGetSymbolAddress(&dthw_c, g_dthw_c);
    cudaGetSymbolAddress(&yg_c, g_yg_c);
    cudaGetSymbolAddress(&opw_c, g_opw_c);

    // 0) fused fp16 converts: hs, in_proj_w, x_proj_w, out_proj, dt_head_w(pad)
    {
        int n0 = Mz * DM, n1 = DI2 * DM, n2 = XDB * DI, n3 = DM * DI, n4 = DI * RKP;
        int g0 = (n0 + 255) / 256, g1 = (n1 + 255) / 256, g2 = (n2 + 255) / 256,
            g3 = (n3 + 255) / 256, g4 = (n4 + 255) / 256;
        cvt5_kernel<<<g0 + g1 + g2 + g3 + g4, 256>>>(
            hs, (__half*)hs_c, n0, g0,
            in_proj_w, (__half*)ipw_c, n1, g0 + g1,
            x_proj_w, (__half*)xpw_c, n2, g0 + g1 + g2,
            out_proj, (__half*)opw_c, n3, g0 + g1 + g2 + g3,
            dt_head_w, (__half*)dthw_c, n4);
    }

    // 1) xz = hs @ in_proj^T  (2048 x 3072, K=768)
    mma_gemm<<<dim3(DI2 / 128, Mz / 128, 1), 256, SMEMB>>>(
        (const __half*)hs_c, (const __half*)ipw_c, (float*)p_xz, DI2, DM, DM, DI2, 0);
    // 2) conv + SiLU
    conv_silu_kernel<<<dim3(DI / 128, Lz / 16, Bz), 128>>>(conv_w, conv_b);
    // 3) x_dbl split-K partials (16-way)
    mma_gemm<<<dim3(1, Mz / 128, NSPK), 256, SMEMB>>>(
        (const __half*)xact_c, (const __half*)xpw_c, (float*)p_xdp,
        XDB, DI / NSPK, DI, XDB, Mz * XDB);
    // 3b) reduce -> knq + dtl
    xdbl_reduce_kernel<<<(Mz * 96 + 255) / 256, 256>>>();
    // 4) dt = dt_low @ dt_head^T  (K=64 padded)
    mma_gemm<<<dim3(DI / 128, Mz / 128, 1), 256, SMEMB>>>(
        (const __half*)dtl_c, (const __half*)dthw_c, (float*)p_dt, DI, RKP, RKP, DI, 0);
    // 5) prep
    prep_kernel<<<Mz, 256>>>(dt_head_b, Dv);
    // 6) scan
    scan_kernel<<<dim3(DI / 16, Bz), 64>>>();
    // 7) out = yg @ out_proj^T
    mma_gemm<<<dim3(DM / 128, Mz / 128, 1), 256, SMEMB>>>(
        (const __half*)yg_c, (const __half*)opw_c, out, DM, DI, DI, DM, 0);
}